// round 15
// baseline (speedup 1.0000x reference)
#include <cuda_runtime.h>
#include <math.h>

#define VOC      50257
#define VOC_BULK 50256           // divisible by 8
#define OCT_V    (VOC_BULK / 8)  // 6282 vocab row-octets
#define EMB      128
#define N_MEM    8192
#define OCT_M    (N_MEM / 8)     // 1024 memory row-octets
#define OCT_W    (EMB / 8)       // 16 Wt_w row-octets
#define NTASK    (OCT_V + OCT_M + 1 + OCT_W)   // unified pv task space
#define T_Q      50
#define T_M      50
#define N_HOPS   3

#define NBV  592                 // stream blocks (4/SM, one wave)
#define TBV  256
#define WPB  8
#define NWV  (NBV * WPB)         // 4736 warps

#define NBM  256                 // memory-space kernel: 256 x 256 = 2048 warps
#define TBM  256
#define MWARPS (NBM * (TBM / 32))

#define SHIFT 24.0f              // constant softmax shift (cancels exactly)
#define NEGBIG (-1e30f)

// ---------------- scratch ----------------
__device__ __align__(16) float g_uarr[N_HOPS][EMB];   // u after hop-h prelude gate
__device__ __align__(16) float g_pv[VOC + 8];
__device__ __align__(16) float g_sTA[N_MEM];
__device__ __align__(16) float g_cw[VOC + 8];
__device__ __align__(16) float g_wo[EMB];
__device__ __align__(16) float g_dt[2][EMB];          // Wt_w . u, parity-buffered
__device__ __align__(16) float g_dh[EMB];             // H_w . swo
__device__ float g_den;
__device__ float g_plmax[NBV];
__device__ float g_plden[NBV];
__device__ unsigned g_ctr_wo;

__device__ __forceinline__ float dot4(float4 a, float4 b) {
    return fmaf(a.x, b.x, fmaf(a.y, b.y, fmaf(a.z, b.z, a.w * b.w)));
}
__device__ __forceinline__ float warp_sum(float p) {
#pragma unroll
    for (int o = 16; o; o >>= 1) p += __shfl_xor_sync(0xFFFFFFFFu, p, o);
    return p;
}
__device__ __forceinline__ void oct_reduce(float* p) {
#pragma unroll
    for (int o = 16; o; o >>= 1) {
#pragma unroll
        for (int j = 0; j < 8; j++)
            p[j] += __shfl_xor_sync(0xFFFFFFFFu, p[j], o);
    }
}
__device__ __forceinline__ void oct_dot(const float* __restrict__ W, long row0,
                                        float4 uu, int lane, float* p) {
    const float4* a = (const float4*)(W + row0 * EMB);
    float4 v[8];
#pragma unroll
    for (int j = 0; j < 8; j++) v[j] = a[j * 32 + lane];
#pragma unroll
    for (int j = 0; j < 8; j++) p[j] = dot4(v[j], uu);
    oct_reduce(p);
}

// redundant elementwise gate: u_h = u_{h-1}*(1-t) + (dh+H_b)*t, t = sigmoid(dt+Wt_b)
__device__ __forceinline__ float gate_elem(int hop, int e,
                                           const float* __restrict__ Wt_b,
                                           const float* __restrict__ H_b) {
    float t = 1.f / (1.f + __expf(-(g_dt[(hop - 1) & 1][e] + Wt_b[e])));
    return g_uarr[hop - 1][e] * (1.f - t) + (g_dh[e] + H_b[e]) * t;
}

// ---------------- pv = Wa.u ; sTA = TA.u ; dt = Wt_w.u ; gate prelude ; zero scratch ----------------
__global__ void __launch_bounds__(TBV) k_pv(int hop,
                                            const float* __restrict__ Wa,
                                            const float* __restrict__ TA,
                                            const float* __restrict__ Wt_w,
                                            const int* __restrict__ query,
                                            const float* __restrict__ Wb,
                                            const float* __restrict__ Wt_b,
                                            const float* __restrict__ H_b) {
    __shared__ __align__(16) float su[EMB];
    __shared__ int stok[T_Q];
    int tid = threadIdx.x, lane = tid & 31, wid = tid >> 5;

    int gid = blockIdx.x * TBV + tid;
    if (gid < VOC) g_cw[gid] = 0.f;
    if (blockIdx.x == 1) {
        if (tid < EMB) g_wo[tid] = 0.f;
        if (tid == EMB) g_den = 0.f;
    }

    if (hop == 0) {
        // redundant per-block u0 = sum_t Wb[query[t]]
        if (tid < T_Q) stok[tid] = query[tid];
        __syncthreads();
        if (tid < EMB) {
            float a = 0.f;
#pragma unroll 10
            for (int t = 0; t < T_Q; t++) a += Wb[(long)stok[t] * EMB + tid];
            su[tid] = a;
            if (blockIdx.x == 0) g_uarr[0][tid] = a;
        }
    } else {
        if (tid < EMB) {
            float un = gate_elem(hop, tid, Wt_b, H_b);
            su[tid] = un;
            if (blockIdx.x == 0) g_uarr[hop][tid] = un;
        }
    }
    __syncthreads();
    float4 uu = ((const float4*)su)[lane];
    int gw = blockIdx.x * WPB + wid;

    // tasks: [0,OCT_V) Wa ; [OCT_V,+OCT_M) TA ; +1 tail row ; [.., +OCT_W) Wt_w
    for (int task = gw; task < NTASK; task += NWV) {
        float p[8];
        if (task < OCT_V) {
            oct_dot(Wa, (long)task * 8, uu, lane, p);
            if (lane == 0) {
                float4* dst = (float4*)(g_pv + task * 8);
                dst[0] = make_float4(p[0], p[1], p[2], p[3]);
                dst[1] = make_float4(p[4], p[5], p[6], p[7]);
            }
        } else if (task < OCT_V + OCT_M) {
            int oc = task - OCT_V;
            oct_dot(TA, (long)oc * 8, uu, lane, p);
            if (lane == 0) {
                float4* dst = (float4*)(g_sTA + oc * 8);
                dst[0] = make_float4(p[0], p[1], p[2], p[3]);
                dst[1] = make_float4(p[4], p[5], p[6], p[7]);
            }
        } else if (task == OCT_V + OCT_M) {   // vocab tail row
            float pt = warp_sum(dot4(((const float4*)(Wa + (long)VOC_BULK * EMB))[lane], uu));
            if (lane == 0) g_pv[VOC_BULK] = pt;
        } else {                               // Wt_w octet -> g_dt[hop parity]
            int oc = task - (OCT_V + OCT_M + 1);
            oct_dot(Wt_w, (long)oc * 8, uu, lane, p);
            if (lane == 0) {
                float4* dst = (float4*)(g_dt[hop & 1] + oc * 8);
                dst[0] = make_float4(p[0], p[1], p[2], p[3]);
                dst[1] = make_float4(p[4], p[5], p[6], p[7]);
            }
        }
    }
}

// ---------------- hop memory phase: warp per memory (lane-parallel gathers) ----------------
__global__ void __launch_bounds__(TBM) k_hopmem(const int* __restrict__ story,
                                                const float* __restrict__ TC) {
    __shared__ float sacc[TBM / 32][EMB];
    int tid = threadIdx.x, lane = tid & 31, wid = tid >> 5;
    int gw = blockIdx.x * (TBM / 32) + wid;

    float dloc = 0.f;
    float4 acc = make_float4(0.f, 0.f, 0.f, 0.f);
#pragma unroll
    for (int r = 0; r < N_MEM / MWARPS; r++) {
        int n = gw + r * MWARPS;
        const int* srow = story + (long)n * T_M;
        int tok0 = srow[lane];
        float sp = __ldg(g_pv + tok0);
        int tok1 = -1;
        if (lane < T_M - 32) {
            tok1 = srow[32 + lane];
            sp += __ldg(g_pv + tok1);
        }
        float s = warp_sum(sp) + g_sTA[n];
        float w = __expf(s - SHIFT);
        if (lane == 0) dloc += w;
        atomicAdd(&g_cw[tok0], w);
        if (tok1 >= 0) atomicAdd(&g_cw[tok1], w);
        float4 v = ((const float4*)(TC + (long)n * EMB))[lane];
        acc.x = fmaf(w, v.x, acc.x);
        acc.y = fmaf(w, v.y, acc.y);
        acc.z = fmaf(w, v.z, acc.z);
        acc.w = fmaf(w, v.w, acc.w);
    }
    if (lane == 0) atomicAdd(&g_den, dloc);
    sacc[wid][lane * 4 + 0] = acc.x;
    sacc[wid][lane * 4 + 1] = acc.y;
    sacc[wid][lane * 4 + 2] = acc.z;
    sacc[wid][lane * 4 + 3] = acc.w;
    __syncthreads();
    if (tid < EMB) {
        float v = 0.f;
#pragma unroll
        for (int w2 = 0; w2 < TBM / 32; w2++) v += sacc[w2][tid];
        atomicAdd(&g_wo[tid], v);
    }
}

// ---------------- wo += Wc^T.cw ; last block: dh = H_w.(wo/den) ----------------
__global__ void __launch_bounds__(TBV) k_wo(const float* __restrict__ Wc,
                                            const float* __restrict__ H_w) {
    __shared__ float sacc[WPB][EMB];
    __shared__ int slast;
    int tid = threadIdx.x, lane = tid & 31, wid = tid >> 5;
    int gw = blockIdx.x * WPB + wid;

    float4 acc = make_float4(0.f, 0.f, 0.f, 0.f);
    for (int oc = gw; oc < OCT_V; oc += NWV) {
        const float4* a = (const float4*)(Wc + (long)oc * 8 * EMB);
        float4 c4a = ((const float4*)g_cw)[oc * 2 + 0];
        float4 c4b = ((const float4*)g_cw)[oc * 2 + 1];
        float4 v[8];
#pragma unroll
        for (int j = 0; j < 8; j++) v[j] = a[j * 32 + lane];
        float c[8] = {c4a.x, c4a.y, c4a.z, c4a.w, c4b.x, c4b.y, c4b.z, c4b.w};
#pragma unroll
        for (int j = 0; j < 8; j++) {
            acc.x = fmaf(c[j], v[j].x, acc.x);
            acc.y = fmaf(c[j], v[j].y, acc.y);
            acc.z = fmaf(c[j], v[j].z, acc.z);
            acc.w = fmaf(c[j], v[j].w, acc.w);
        }
    }
    if (gw == 0) {   // tail row
        float c = g_cw[VOC_BULK];
        float4 v = ((const float4*)(Wc + (long)VOC_BULK * EMB))[lane];
        acc.x = fmaf(c, v.x, acc.x); acc.y = fmaf(c, v.y, acc.y);
        acc.z = fmaf(c, v.z, acc.z); acc.w = fmaf(c, v.w, acc.w);
    }
    sacc[wid][lane * 4 + 0] = acc.x;
    sacc[wid][lane * 4 + 1] = acc.y;
    sacc[wid][lane * 4 + 2] = acc.z;
    sacc[wid][lane * 4 + 3] = acc.w;
    __syncthreads();
    if (tid < EMB) {
        float v = 0.f;
#pragma unroll
        for (int w2 = 0; w2 < WPB; w2++) v += sacc[w2][tid];
        if (v != 0.f) atomicAdd(&g_wo[tid], v);
    }
    __threadfence();
    if (tid == 0) slast = (atomicAdd(&g_ctr_wo, 1u) == (unsigned)(gridDim.x - 1));
    __syncthreads();
    if (!slast) return;

    // ---- last block: dh = H_w.(wo/den), 8 warps x 2 octets = 128 rows ----
    __shared__ __align__(16) float swo[EMB];
    if (tid < EMB) swo[tid] = g_wo[tid] / g_den;
    __syncthreads();
    {
        float4 v4 = ((const float4*)swo)[lane];
#pragma unroll
        for (int r = 0; r < 2; r++) {
            int oc = wid * 2 + r;                        // 16 octets
            float p[8];
            oct_dot(H_w, (long)oc * 8, v4, lane, p);
            if (lane < 8) g_dh[oc * 8 + lane] = p[lane];
        }
    }
    if (tid == 0) g_ctr_wo = 0u;
}

// ---------------- logits + online partials (gate prelude) ----------------
__global__ void __launch_bounds__(TBV) k_logits(const float* __restrict__ wout,
                                                const float* __restrict__ Wt_b,
                                                const float* __restrict__ H_b,
                                                float* __restrict__ out) {
    __shared__ __align__(16) float su[EMB];
    __shared__ float sm[WPB], sd[WPB];
    int tid = threadIdx.x, lane = tid & 31, wid = tid >> 5;
    if (tid < EMB) su[tid] = gate_elem(N_HOPS, tid, Wt_b, H_b);   // parity (N_HOPS-1)&1
    __syncthreads();
    float4 uu = ((const float4*)su)[lane];
    int gw = blockIdx.x * WPB + wid;

    float m = NEGBIG, d = 0.f;
    if (gw == 0) {   // tail row
        float p = warp_sum(dot4(((const float4*)(wout + (long)VOC_BULK * EMB))[lane], uu));
        if (lane == 0) out[VOC_BULK] = p;
        m = p; d = 1.f;
    }
    for (int oc = gw; oc < OCT_V; oc += NWV) {
        float p[8];
        oct_dot(wout, (long)oc * 8, uu, lane, p);
        if (lane == 0) {
            float4* dst = (float4*)(out + oc * 8);
            dst[0] = make_float4(p[0], p[1], p[2], p[3]);
            dst[1] = make_float4(p[4], p[5], p[6], p[7]);
        }
        float mx = p[0];
#pragma unroll
        for (int j = 1; j < 8; j++) mx = fmaxf(mx, p[j]);
        float mn = fmaxf(m, mx);
        float dn = d * __expf(m - mn);
#pragma unroll
        for (int j = 0; j < 8; j++) dn += __expf(p[j] - mn);
        m = mn; d = dn;
    }
    if (lane == 0) { sm[wid] = m; sd[wid] = d; }
    __syncthreads();
    if (tid < 32) {
        float mm = (tid < WPB) ? sm[tid] : NEGBIG;
        float dd = (tid < WPB) ? sd[tid] : 0.f;
#pragma unroll
        for (int o = 4; o; o >>= 1) {
            float mo  = __shfl_xor_sync(0xFFFFFFFFu, mm, o);
            float ddo = __shfl_xor_sync(0xFFFFFFFFu, dd, o);
            float mn  = fmaxf(mm, mo);
            dd = dd * __expf(mm - mn) + ddo * __expf(mo - mn);
            mm = mn;
        }
        if (tid == 0) { g_plmax[blockIdx.x] = mm; g_plden[blockIdx.x] = dd; }
    }
}

// ---------------- combine partials + normalize ----------------
__global__ void k_norm(float* __restrict__ out) {
    __shared__ float sc;
    int tid = threadIdx.x, lane = tid & 31;
    if (tid < 32) {
        float mm = NEGBIG, dd = 0.f;
        for (int b = lane; b < NBV; b += 32) {
            float mo = g_plmax[b], ddo = g_plden[b];
            float mn = fmaxf(mm, mo);
            dd = dd * __expf(mm - mn) + ddo * __expf(mo - mn);
            mm = mn;
        }
#pragma unroll
        for (int o = 16; o; o >>= 1) {
            float mo  = __shfl_xor_sync(0xFFFFFFFFu, mm, o);
            float ddo = __shfl_xor_sync(0xFFFFFFFFu, dd, o);
            float mn  = fmaxf(mm, mo);
            dd = dd * __expf(mm - mn) + ddo * __expf(mo - mn);
            mm = mn;
        }
        if (tid == 0) sc = mm + logf(dd);
    }
    __syncthreads();
    float c = sc;
    float4* o4 = (float4*)out;
    for (int i = blockIdx.x * blockDim.x + tid; i < VOC_BULK / 4; i += gridDim.x * blockDim.x) {
        float4 v = o4[i];
        v.x -= c; v.y -= c; v.z -= c; v.w -= c;
        o4[i] = v;
    }
    if (blockIdx.x == 0 && tid == 0) out[VOC_BULK] -= c;
}

// ---------------- launch ----------------
extern "C" void kernel_launch(void* const* d_in, const int* in_sizes, int n_in,
                              void* d_out, int out_size) {
    const int*   query = (const int*)  d_in[0];
    const int*   story = (const int*)  d_in[1];
    const float* Wa    = (const float*)d_in[2];
    const float* Wc    = (const float*)d_in[3];
    const float* Wb    = (const float*)d_in[4];
    const float* Wt_w  = (const float*)d_in[5];
    const float* Wt_b  = (const float*)d_in[6];
    const float* H_w   = (const float*)d_in[7];
    const float* H_b   = (const float*)d_in[8];
    const float* wout  = (const float*)d_in[9];
    const float* TA    = (const float*)d_in[10];
    const float* TC    = (const float*)d_in[11];
    float* out = (float*)d_out;

    for (int h = 0; h < N_HOPS; h++) {
        k_pv    <<<NBV, TBV>>>(h, Wa, TA, Wt_w, query, Wb, Wt_b, H_b);
        k_hopmem<<<NBM, TBM>>>(story, TC);
        k_wo    <<<NBV, TBV>>>(Wc, H_w);
    }

    k_logits<<<NBV, TBV>>>(wout, Wt_b, H_b, out);
    k_norm  <<<148, 256>>>(out);
}

// round 16
// speedup vs baseline: 1.2131x; 1.2131x over previous
#include <cuda_runtime.h>
#include <math.h>

#define VOC      50257
#define VOC_BULK 50256           // divisible by 8
#define OCT_V    (VOC_BULK / 8)  // 6282 vocab row-octets
#define EMB      128
#define N_MEM    8192
#define OCT_M    (N_MEM / 8)     // 1024 memory row-octets
#define OCT_W    (EMB / 8)       // 16 Wt_w row-octets
#define NTASK    (OCT_V + OCT_M + 1 + OCT_W)   // unified pv task space
#define T_Q      50
#define T_M      50
#define N_HOPS   3

#define NBV  592                 // stream blocks (4/SM, one wave)
#define TBV  256
#define WPB  8
#define NWV  (NBV * WPB)         // 4736 warps

#define NBM  512                 // memory-space kernel: 512 x 256 = 4096 warps
#define TBM  256
#define MWARPS (NBM * (TBM / 32))

#define SHIFT 24.0f              // constant softmax shift (cancels exactly)
#define NEGBIG (-1e30f)

// ---------------- scratch ----------------
__device__ __align__(16) float g_uarr[N_HOPS][EMB];   // u after hop-h prelude gate
__device__ __align__(16) float g_pv[VOC + 8];
__device__ __align__(16) float g_sTA[N_MEM];
__device__ __align__(16) float g_cw[VOC + 8];
__device__ __align__(16) float g_wo[EMB];
__device__ __align__(16) float g_dt[2][EMB];          // Wt_w . u, parity-buffered
__device__ __align__(16) float g_dh[EMB];             // H_w . swo
__device__ float g_den;
__device__ float g_plmax[NBV];
__device__ float g_plden[NBV];

__device__ __forceinline__ float dot4(float4 a, float4 b) {
    return fmaf(a.x, b.x, fmaf(a.y, b.y, fmaf(a.z, b.z, a.w * b.w)));
}
__device__ __forceinline__ float warp_sum(float p) {
#pragma unroll
    for (int o = 16; o; o >>= 1) p += __shfl_xor_sync(0xFFFFFFFFu, p, o);
    return p;
}
__device__ __forceinline__ void oct_reduce(float* p) {
#pragma unroll
    for (int o = 16; o; o >>= 1) {
#pragma unroll
        for (int j = 0; j < 8; j++)
            p[j] += __shfl_xor_sync(0xFFFFFFFFu, p[j], o);
    }
}
__device__ __forceinline__ void oct_dot(const float* __restrict__ W, long row0,
                                        float4 uu, int lane, float* p) {
    const float4* a = (const float4*)(W + row0 * EMB);
    float4 v[8];
#pragma unroll
    for (int j = 0; j < 8; j++) v[j] = a[j * 32 + lane];
#pragma unroll
    for (int j = 0; j < 8; j++) p[j] = dot4(v[j], uu);
    oct_reduce(p);
}

// redundant elementwise gate: u_h = u_{h-1}*(1-t) + (dh+H_b)*t, t = sigmoid(dt+Wt_b)
__device__ __forceinline__ float gate_elem(int hop, int e,
                                           const float* __restrict__ Wt_b,
                                           const float* __restrict__ H_b) {
    float t = 1.f / (1.f + __expf(-(g_dt[(hop - 1) & 1][e] + Wt_b[e])));
    return g_uarr[hop - 1][e] * (1.f - t) + (g_dh[e] + H_b[e]) * t;
}

// ---------------- pv = Wa.u ; sTA = TA.u ; dt = Wt_w.u ; gate prelude ; zero scratch ----------------
__global__ void __launch_bounds__(TBV) k_pv(int hop,
                                            const float* __restrict__ Wa,
                                            const float* __restrict__ TA,
                                            const float* __restrict__ Wt_w,
                                            const int* __restrict__ query,
                                            const float* __restrict__ Wb,
                                            const float* __restrict__ Wt_b,
                                            const float* __restrict__ H_b) {
    __shared__ __align__(16) float su[EMB];
    __shared__ int stok[T_Q];
    int tid = threadIdx.x, lane = tid & 31, wid = tid >> 5;

    int gid = blockIdx.x * TBV + tid;
    if (gid < VOC) g_cw[gid] = 0.f;
    if (blockIdx.x == 1) {
        if (tid < EMB) g_wo[tid] = 0.f;
        if (tid == EMB) g_den = 0.f;
    }

    if (hop == 0) {
        // redundant per-block u0 = sum_t Wb[query[t]]
        if (tid < T_Q) stok[tid] = query[tid];
        __syncthreads();
        if (tid < EMB) {
            float a = 0.f;
#pragma unroll 10
            for (int t = 0; t < T_Q; t++) a += Wb[(long)stok[t] * EMB + tid];
            su[tid] = a;
            if (blockIdx.x == 0) g_uarr[0][tid] = a;
        }
    } else {
        if (tid < EMB) {
            float un = gate_elem(hop, tid, Wt_b, H_b);
            su[tid] = un;
            if (blockIdx.x == 0) g_uarr[hop][tid] = un;
        }
    }
    __syncthreads();
    float4 uu = ((const float4*)su)[lane];
    int gw = blockIdx.x * WPB + wid;

    // tasks: [0,OCT_V) Wa ; [OCT_V,+OCT_M) TA ; +1 tail row ; [.., +OCT_W) Wt_w
    for (int task = gw; task < NTASK; task += NWV) {
        float p[8];
        if (task < OCT_V) {
            oct_dot(Wa, (long)task * 8, uu, lane, p);
            if (lane == 0) {
                float4* dst = (float4*)(g_pv + task * 8);
                dst[0] = make_float4(p[0], p[1], p[2], p[3]);
                dst[1] = make_float4(p[4], p[5], p[6], p[7]);
            }
        } else if (task < OCT_V + OCT_M) {
            int oc = task - OCT_V;
            oct_dot(TA, (long)oc * 8, uu, lane, p);
            if (lane == 0) {
                float4* dst = (float4*)(g_sTA + oc * 8);
                dst[0] = make_float4(p[0], p[1], p[2], p[3]);
                dst[1] = make_float4(p[4], p[5], p[6], p[7]);
            }
        } else if (task == OCT_V + OCT_M) {   // vocab tail row
            float pt = warp_sum(dot4(((const float4*)(Wa + (long)VOC_BULK * EMB))[lane], uu));
            if (lane == 0) g_pv[VOC_BULK] = pt;
        } else {                               // Wt_w octet -> g_dt[hop parity]
            int oc = task - (OCT_V + OCT_M + 1);
            oct_dot(Wt_w, (long)oc * 8, uu, lane, p);
            if (lane == 0) {
                float4* dst = (float4*)(g_dt[hop & 1] + oc * 8);
                dst[0] = make_float4(p[0], p[1], p[2], p[3]);
                dst[1] = make_float4(p[4], p[5], p[6], p[7]);
            }
        }
    }
}

// ---------------- hop memory phase: warp per memory (lane-parallel gathers) ----------------
__global__ void __launch_bounds__(TBM) k_hopmem(const int* __restrict__ story,
                                                const float* __restrict__ TC) {
    __shared__ float sacc[TBM / 32][EMB];
    __shared__ float sred[TBM / 32];
    int tid = threadIdx.x, lane = tid & 31, wid = tid >> 5;
    int gw = blockIdx.x * (TBM / 32) + wid;

    float dloc = 0.f;
    float4 acc = make_float4(0.f, 0.f, 0.f, 0.f);
#pragma unroll
    for (int r = 0; r < N_MEM / MWARPS; r++) {
        int n = gw + r * MWARPS;
        const int* srow = story + (long)n * T_M;
        int tok0 = srow[lane];
        float sp = __ldg(g_pv + tok0);
        int tok1 = -1;
        if (lane < T_M - 32) {
            tok1 = srow[32 + lane];
            sp += __ldg(g_pv + tok1);
        }
        float s = warp_sum(sp) + g_sTA[n];
        float w = __expf(s - SHIFT);
        if (lane == 0) dloc += w;
        atomicAdd(&g_cw[tok0], w);
        if (tok1 >= 0) atomicAdd(&g_cw[tok1], w);
        float4 v = ((const float4*)(TC + (long)n * EMB))[lane];
        acc.x = fmaf(w, v.x, acc.x);
        acc.y = fmaf(w, v.y, acc.y);
        acc.z = fmaf(w, v.z, acc.z);
        acc.w = fmaf(w, v.w, acc.w);
    }
    if (lane == 0) sred[wid] = dloc;
    sacc[wid][lane * 4 + 0] = acc.x;
    sacc[wid][lane * 4 + 1] = acc.y;
    sacc[wid][lane * 4 + 2] = acc.z;
    sacc[wid][lane * 4 + 3] = acc.w;
    __syncthreads();
    if (tid == 0) {
        float db = 0.f;
#pragma unroll
        for (int i = 0; i < TBM / 32; i++) db += sred[i];
        atomicAdd(&g_den, db);
    }
    if (tid < EMB) {
        float v = 0.f;
#pragma unroll
        for (int w2 = 0; w2 < TBM / 32; w2++) v += sacc[w2][tid];
        atomicAdd(&g_wo[tid], v);
    }
}

// ---------------- wo += Wc^T.cw (R8 body) ----------------
__global__ void __launch_bounds__(TBV) k_wo(const float* __restrict__ Wc) {
    __shared__ float sacc[WPB][EMB];
    int tid = threadIdx.x, lane = tid & 31, wid = tid >> 5;
    int gw = blockIdx.x * WPB + wid;

    float4 acc = make_float4(0.f, 0.f, 0.f, 0.f);
    for (int oc = gw; oc < OCT_V; oc += NWV) {
        const float4* a = (const float4*)(Wc + (long)oc * 8 * EMB);
        float4 c4a = ((const float4*)g_cw)[oc * 2 + 0];
        float4 c4b = ((const float4*)g_cw)[oc * 2 + 1];
        float4 v[8];
#pragma unroll
        for (int j = 0; j < 8; j++) v[j] = a[j * 32 + lane];
        float c[8] = {c4a.x, c4a.y, c4a.z, c4a.w, c4b.x, c4b.y, c4b.z, c4b.w};
#pragma unroll
        for (int j = 0; j < 8; j++) {
            acc.x = fmaf(c[j], v[j].x, acc.x);
            acc.y = fmaf(c[j], v[j].y, acc.y);
            acc.z = fmaf(c[j], v[j].z, acc.z);
            acc.w = fmaf(c[j], v[j].w, acc.w);
        }
    }
    if (gw == 0) {   // tail row
        float c = g_cw[VOC_BULK];
        float4 v = ((const float4*)(Wc + (long)VOC_BULK * EMB))[lane];
        acc.x = fmaf(c, v.x, acc.x); acc.y = fmaf(c, v.y, acc.y);
        acc.z = fmaf(c, v.z, acc.z); acc.w = fmaf(c, v.w, acc.w);
    }
    sacc[wid][lane * 4 + 0] = acc.x;
    sacc[wid][lane * 4 + 1] = acc.y;
    sacc[wid][lane * 4 + 2] = acc.z;
    sacc[wid][lane * 4 + 3] = acc.w;
    __syncthreads();
    if (tid < EMB) {
        float v = 0.f;
#pragma unroll
        for (int w2 = 0; w2 < WPB; w2++) v += sacc[w2][tid];
        if (v != 0.f) atomicAdd(&g_wo[tid], v);
    }
}

// ---------------- dh = H_w . (wo/den): 16 blocks x 8 warps = warp per row ----------------
__global__ void __launch_bounds__(256) k_dh(const float* __restrict__ H_w) {
    int tid = threadIdx.x, lane = tid & 31, wid = tid >> 5;
    int row = blockIdx.x * 8 + wid;                     // 16*8 = 128 rows
    float4 wo4 = make_float4(g_wo[lane * 4 + 0], g_wo[lane * 4 + 1],
                             g_wo[lane * 4 + 2], g_wo[lane * 4 + 3]);
    float inv = 1.f / g_den;
    wo4.x *= inv; wo4.y *= inv; wo4.z *= inv; wo4.w *= inv;
    float p = warp_sum(dot4(((const float4*)(H_w + (long)row * EMB))[lane], wo4));
    if (lane == 0) g_dh[row] = p;
}

// ---------------- logits + online partials (gate prelude) ----------------
__global__ void __launch_bounds__(TBV) k_logits(const float* __restrict__ wout,
                                                const float* __restrict__ Wt_b,
                                                const float* __restrict__ H_b,
                                                float* __restrict__ out) {
    __shared__ __align__(16) float su[EMB];
    __shared__ float sm[WPB], sd[WPB];
    int tid = threadIdx.x, lane = tid & 31, wid = tid >> 5;
    if (tid < EMB) su[tid] = gate_elem(N_HOPS, tid, Wt_b, H_b);   // parity (N_HOPS-1)&1
    __syncthreads();
    float4 uu = ((const float4*)su)[lane];
    int gw = blockIdx.x * WPB + wid;

    float m = NEGBIG, d = 0.f;
    if (gw == 0) {   // tail row
        float p = warp_sum(dot4(((const float4*)(wout + (long)VOC_BULK * EMB))[lane], uu));
        if (lane == 0) out[VOC_BULK] = p;
        m = p; d = 1.f;
    }
    for (int oc = gw; oc < OCT_V; oc += NWV) {
        float p[8];
        oct_dot(wout, (long)oc * 8, uu, lane, p);
        if (lane == 0) {
            float4* dst = (float4*)(out + oc * 8);
            dst[0] = make_float4(p[0], p[1], p[2], p[3]);
            dst[1] = make_float4(p[4], p[5], p[6], p[7]);
        }
        float mx = p[0];
#pragma unroll
        for (int j = 1; j < 8; j++) mx = fmaxf(mx, p[j]);
        float mn = fmaxf(m, mx);
        float dn = d * __expf(m - mn);
#pragma unroll
        for (int j = 0; j < 8; j++) dn += __expf(p[j] - mn);
        m = mn; d = dn;
    }
    if (lane == 0) { sm[wid] = m; sd[wid] = d; }
    __syncthreads();
    if (tid < 32) {
        float mm = (tid < WPB) ? sm[tid] : NEGBIG;
        float dd = (tid < WPB) ? sd[tid] : 0.f;
#pragma unroll
        for (int o = 4; o; o >>= 1) {
            float mo  = __shfl_xor_sync(0xFFFFFFFFu, mm, o);
            float ddo = __shfl_xor_sync(0xFFFFFFFFu, dd, o);
            float mn  = fmaxf(mm, mo);
            dd = dd * __expf(mm - mn) + ddo * __expf(mo - mn);
            mm = mn;
        }
        if (tid == 0) { g_plmax[blockIdx.x] = mm; g_plden[blockIdx.x] = dd; }
    }
}

// ---------------- combine partials (block-parallel) + normalize ----------------
__global__ void k_norm(float* __restrict__ out) {
    __shared__ float smm[8], sdm[8];
    __shared__ float sc;
    int tid = threadIdx.x, lane = tid & 31, wid = tid >> 5;

    // 256 threads fold 592 partials (2-3 each), then warp+block combine
    float mm = NEGBIG, dd = 0.f;
    for (int b = tid; b < NBV; b += 256) {
        float mo = g_plmax[b], ddo = g_plden[b];
        float mn = fmaxf(mm, mo);
        dd = dd * __expf(mm - mn) + ddo * __expf(mo - mn);
        mm = mn;
    }
#pragma unroll
    for (int o = 16; o; o >>= 1) {
        float mo  = __shfl_xor_sync(0xFFFFFFFFu, mm, o);
        float ddo = __shfl_xor_sync(0xFFFFFFFFu, dd, o);
        float mn  = fmaxf(mm, mo);
        dd = dd * __expf(mm - mn) + ddo * __expf(mo - mn);
        mm = mn;
    }
    if (lane == 0) { smm[wid] = mm; sdm[wid] = dd; }
    __syncthreads();
    if (tid == 0) {
        float M = smm[0], D = sdm[0];
#pragma unroll
        for (int w2 = 1; w2 < 8; w2++) {
            float mn = fmaxf(M, smm[w2]);
            D = D * __expf(M - mn) + sdm[w2] * __expf(smm[w2] - mn);
            M = mn;
        }
        sc = M + logf(D);
    }
    __syncthreads();
    float c = sc;
    float4* o4 = (float4*)out;
    for (int i = blockIdx.x * blockDim.x + tid; i < VOC_BULK / 4; i += gridDim.x * blockDim.x) {
        float4 v = o4[i];
        v.x -= c; v.y -= c; v.z -= c; v.w -= c;
        o4[i] = v;
    }
    if (blockIdx.x == 0 && tid == 0) out[VOC_BULK] -= c;
}

// ---------------- launch ----------------
extern "C" void kernel_launch(void* const* d_in, const int* in_sizes, int n_in,
                              void* d_out, int out_size) {
    const int*   query = (const int*)  d_in[0];
    const int*   story = (const int*)  d_in[1];
    const float* Wa    = (const float*)d_in[2];
    const float* Wc    = (const float*)d_in[3];
    const float* Wb    = (const float*)d_in[4];
    const float* Wt_w  = (const float*)d_in[5];
    const float* Wt_b  = (const float*)d_in[6];
    const float* H_w   = (const float*)d_in[7];
    const float* H_b   = (const float*)d_in[8];
    const float* wout  = (const float*)d_in[9];
    const float* TA    = (const float*)d_in[10];
    const float* TC    = (const float*)d_in[11];
    float* out = (float*)d_out;

    for (int h = 0; h < N_HOPS; h++) {
        k_pv    <<<NBV, TBV>>>(h, Wa, TA, Wt_w, query, Wb, Wt_b, H_b);
        k_hopmem<<<NBM, TBM>>>(story, TC);
        k_wo    <<<NBV, TBV>>>(Wc);
        k_dh    <<<16, 256>>>(H_w);
    }

    k_logits<<<NBV, TBV>>>(wout, Wt_b, H_b, out);
    k_norm  <<<148, 256>>>(out);
}